// round 1
// baseline (speedup 1.0000x reference)
#include <cuda_runtime.h>
#include <cstdint>

// Problem constants (fixed by reference setup_inputs)
#define D    64      // input feature dim
#define H1   128     // hidden 1
#define H2   64      // hidden 2
#define NMAX 1024
#define EPS_F 1e-10f

// Scratch (no allocations allowed)
__device__ float g_A[NMAX * H1];   // X @ W1[:D]  + b1   (per-i contribution)
__device__ float g_B[NMAX * H1];   // X @ W1[D:]          (per-j contribution)
__device__ float g_L[NMAX * NMAX]; // ldiff[i,j] = l1 - l0 for ordered pair (i,j)

// ---------------------------------------------------------------------------
// Kernel 1: A[i,k] = b1[k] + sum_d X[i,d] * W1[d,k]
//           B[i,k] =         sum_d X[i,d] * W1[D+d,k]
// One block per row i, 128 threads (one per k).
// ---------------------------------------------------------------------------
__global__ void ab_kernel(const float* __restrict__ X,
                          const float* __restrict__ W1,
                          const float* __restrict__ b1,
                          int n)
{
    __shared__ float xs[D];
    const int i = blockIdx.x;
    const int k = threadIdx.x;
    if (k < D) xs[k] = X[i * D + k];
    __syncthreads();

    float a = b1[k];
    float b = 0.0f;
#pragma unroll
    for (int d = 0; d < D; d++) {
        const float x = xs[d];
        a = fmaf(x, W1[d * H1 + k], a);
        b = fmaf(x, W1[(D + d) * H1 + k], b);
    }
    g_A[i * H1 + k] = a;
    g_B[i * H1 + k] = b;
}

// ---------------------------------------------------------------------------
// Kernel 2: for each pair (i,j):
//   h1 = relu(A[i] + B[j])            (b1 already folded into A)
//   h2 = relu(h1 @ W2 + b2)
//   L[i,j] = (h2 . (W3[:,1]-W3[:,0])) + (b3[1]-b3[0])
// Block = 256 threads = 16x16 pair tile. One thread per pair.
// 64 accumulators kept as 32 packed f32x2 registers; inner loop uses
// fma.rn.f32x2 (FFMA2) -> 32 packed FMA + 16 broadcast LDS.128 per k.
// ---------------------------------------------------------------------------
#define TILE 16
#define SMEM_W2   (H1 * H2)          // 8192 floats
#define SMEM_AB   (H1 * (TILE + 1))  // 2176 floats, pad 17 vs bank conflicts
#define SMEM_FLOATS (SMEM_W2 + 2 * SMEM_AB + H2)
#define SMEM_BYTES  (SMEM_FLOATS * 4)

__global__ __launch_bounds__(256)
void pair_kernel(const float* __restrict__ W2,
                 const float* __restrict__ b2,
                 const float* __restrict__ W3,
                 const float* __restrict__ b3,
                 int n)
{
    extern __shared__ float smem[];
    float* W2s  = smem;                       // [128][64] row-major
    float* As   = smem + SMEM_W2;             // [128][17] (k-major, padded)
    float* Bs   = As + SMEM_AB;               // [128][17]
    float* w3ds = Bs + SMEM_AB;               // [64] : W3[:,1]-W3[:,0]

    const int tid = threadIdx.x;
    const int ti  = tid >> 4;      // i within tile
    const int tj  = tid & 15;      // j within tile
    const int i0  = blockIdx.y * TILE;
    const int j0  = blockIdx.x * TILE;

    // Stage W2 (32 KB), A/B tiles (transposed, padded), w3 diff
    for (int idx = tid; idx < SMEM_W2; idx += 256) W2s[idx] = W2[idx];
    for (int idx = tid; idx < TILE * H1; idx += 256) {
        const int r = idx >> 7;          // row in tile
        const int k = idx & (H1 - 1);    // feature
        As[k * (TILE + 1) + r] = g_A[(i0 + r) * H1 + k];
        Bs[k * (TILE + 1) + r] = g_B[(j0 + r) * H1 + k];
    }
    if (tid < H2) w3ds[tid] = W3[tid * 2 + 1] - W3[tid * 2 + 0];
    __syncthreads();

    // 64 accumulators packed as 32 x f32x2, initialized with b2
    unsigned long long acc[H2 / 2];
    const unsigned long long* b2p = (const unsigned long long*)b2;
#pragma unroll
    for (int m = 0; m < H2 / 2; m++) acc[m] = __ldg(&b2p[m]);

    for (int k = 0; k < H1; k++) {
        float h = fmaxf(As[k * (TILE + 1) + ti] + Bs[k * (TILE + 1) + tj], 0.0f);
        unsigned long long hh;
        asm("mov.b64 %0, {%1, %1};" : "=l"(hh) : "f"(h));
        const double2* w2row = (const double2*)&W2s[k * H2];
#pragma unroll
        for (int q = 0; q < H2 / 4; q++) {          // 16 iterations
            const double2 w = w2row[q];             // LDS.128 broadcast
            asm("fma.rn.f32x2 %0, %1, %2, %0;"
                : "+l"(acc[2 * q])
                : "l"(__double_as_longlong(w.x)), "l"(hh));
            asm("fma.rn.f32x2 %0, %1, %2, %0;"
                : "+l"(acc[2 * q + 1])
                : "l"(__double_as_longlong(w.y)), "l"(hh));
        }
    }

    // Epilogue: relu + dot with (W3[:,1]-W3[:,0])
    float ld = __ldg(&b3[1]) - __ldg(&b3[0]);
#pragma unroll
    for (int m = 0; m < H2 / 2; m++) {
        float lo, hi;
        asm("mov.b64 {%0, %1}, %2;" : "=f"(lo), "=f"(hi) : "l"(acc[m]));
        ld = fmaf(fmaxf(lo, 0.0f), w3ds[2 * m],     ld);
        ld = fmaf(fmaxf(hi, 0.0f), w3ds[2 * m + 1], ld);
    }
    g_L[(i0 + ti) * n + (j0 + tj)] = ld;
}

// ---------------------------------------------------------------------------
// Kernel 3: out[i,j] = ( 0.5*(L[i,j]+L[j,i]) + g1 - g0 > 0 ) ? 1 : 0
// with g = -log(-log(u + EPS) + EPS). Straight-through forward value is the
// hard one-hot; argmax(softmax(z)) == argmax(z); ties -> index 0 -> output 0.
// 32x32 tile with smem transpose for the L[j,i] access.
// ---------------------------------------------------------------------------
__global__ void out_kernel(const float* __restrict__ u,
                           float* __restrict__ out,
                           int n)
{
    __shared__ float Lt[32][33];
    const int tx = threadIdx.x;         // 0..31
    const int ty = threadIdx.y;         // 0..7
    const int i0 = blockIdx.y * 32;
    const int j0 = blockIdx.x * 32;

    // Load the transposed tile: Lt[jj][ii] = L[j0+jj, i0+ii]  (coalesced)
#pragma unroll
    for (int r = 0; r < 4; r++) {
        const int jj = ty + 8 * r;
        Lt[jj][tx] = g_L[(j0 + jj) * n + (i0 + tx)];
    }
    __syncthreads();

#pragma unroll
    for (int r = 0; r < 4; r++) {
        const int ii = ty + 8 * r;
        const int i = i0 + ii;
        const int j = j0 + tx;
        const float lij = g_L[i * n + j];
        const float lji = Lt[tx][ii];
        const float lsym = 0.5f * (lij + lji);
        const float2 uv = ((const float2*)u)[i * n + j];
        const float g0 = -logf(-logf(uv.x + EPS_F) + EPS_F);
        const float g1 = -logf(-logf(uv.y + EPS_F) + EPS_F);
        out[i * n + j] = (lsym + g1 - g0 > 0.0f) ? 1.0f : 0.0f;
    }
}

// ---------------------------------------------------------------------------
extern "C" void kernel_launch(void* const* d_in, const int* in_sizes, int n_in,
                              void* d_out, int out_size)
{
    const float* X  = (const float*)d_in[0];
    const float* W1 = (const float*)d_in[1];
    const float* b1 = (const float*)d_in[2];
    const float* W2 = (const float*)d_in[3];
    const float* b2 = (const float*)d_in[4];
    const float* W3 = (const float*)d_in[5];
    const float* b3 = (const float*)d_in[6];
    const float* u  = (const float*)d_in[7];
    float* out = (float*)d_out;

    const int n = in_sizes[0] / D;   // 1024

    static bool attr_set = false;
    if (!attr_set) {
        cudaFuncSetAttribute(pair_kernel,
                             cudaFuncAttributeMaxDynamicSharedMemorySize,
                             SMEM_BYTES);
        attr_set = true;
    }

    ab_kernel<<<n, H1>>>(X, W1, b1, n);

    dim3 g2(n / TILE, n / TILE);
    pair_kernel<<<g2, 256, SMEM_BYTES>>>(W2, b2, W3, b3, n);

    dim3 b3d(32, 8);
    dim3 g3(n / 32, n / 32);
    out_kernel<<<g3, b3d>>>(u, out, n);
}

// round 2
// speedup vs baseline: 1.4422x; 1.4422x over previous
#include <cuda_runtime.h>
#include <cstdint>

// Problem constants (fixed by reference setup_inputs)
#define D    64      // input feature dim
#define H1   128     // hidden 1
#define H2   64      // hidden 2
#define NMAX 1024
#define EPS_F 1e-10f

// Scratch (no allocations allowed)
__device__ float g_A[NMAX * H1];   // X @ W1[:D]  + b1   (per-i contribution)
__device__ float g_B[NMAX * H1];   // X @ W1[D:]          (per-j contribution)
__device__ float g_L[NMAX * NMAX]; // ldiff[i,j] = l1 - l0 for ordered pair (i,j)

// ---------------------------------------------------------------------------
// Kernel 1: A[i,k] = b1[k] + sum_d X[i,d] * W1[d,k]
//           B[i,k] =         sum_d X[i,d] * W1[D+d,k]
// ---------------------------------------------------------------------------
__global__ void ab_kernel(const float* __restrict__ X,
                          const float* __restrict__ W1,
                          const float* __restrict__ b1,
                          int n)
{
    __shared__ float xs[D];
    const int i = blockIdx.x;
    const int k = threadIdx.x;
    if (k < D) xs[k] = X[i * D + k];
    __syncthreads();

    float a = b1[k];
    float b = 0.0f;
#pragma unroll
    for (int d = 0; d < D; d++) {
        const float x = xs[d];
        a = fmaf(x, W1[d * H1 + k], a);
        b = fmaf(x, W1[(D + d) * H1 + k], b);
    }
    g_A[i * H1 + k] = a;
    g_B[i * H1 + k] = b;
}

// ---------------------------------------------------------------------------
// Kernel 2 (restructured): 16x16 pair tile per block, 256 threads.
// Thread t:  oh  = t >> 7          (which half of H2: outputs [32*oh, 32*oh+32))
//            rem = t & 127
//            ti  = rem >> 3        (i within tile, 0..15)
//            tjg = rem & 7         (j-pair group: j = 2*tjg, 2*tjg+1)
// Each thread: 2 pairs x 32 outputs = 64 fp32 accumulators as 32 f32x2 regs.
// Per k: 3 scalar LDS + 8 broadcast LDS.128 + 32 FFMA2  (was 18 LDS + 32 FFMA2)
// ---------------------------------------------------------------------------
#define TILE 16
#define SM_W2   (H1 * H2)            // 8192
#define SM_AB   (H1 * (TILE + 1))    // 2176 (pad 17)
#define SM_PART (2 * TILE * TILE)    // 512
#define SMEM_FLOATS (SM_W2 + 2 * SM_AB + H2 + SM_PART)
#define SMEM_BYTES  (SMEM_FLOATS * 4)

__global__ __launch_bounds__(256)
void pair_kernel(const float* __restrict__ W2,
                 const float* __restrict__ b2,
                 const float* __restrict__ W3,
                 const float* __restrict__ b3,
                 int n)
{
    extern __shared__ float smem[];
    float* W2s  = smem;                       // [128][64] row-major
    float* As   = smem + SM_W2;               // [128][17] k-major, padded
    float* Bs   = As + SM_AB;                 // [128][17]
    float* w3ds = Bs + SM_AB;                 // [64]
    float* part = w3ds + H2;                  // [2][16][16] partial dots

    const int tid = threadIdx.x;
    const int oh  = tid >> 7;          // H2 half
    const int rem = tid & 127;
    const int ti  = rem >> 3;          // 0..15
    const int tjg = rem & 7;           // 0..7 ; pairs j = 2*tjg, 2*tjg+1
    const int i0  = blockIdx.y * TILE;
    const int j0  = blockIdx.x * TILE;

    // Stage W2 (float4 copies), A/B tiles (transposed, pad 17), w3 diff
    {
        const float4* W2v = (const float4*)W2;
        float4* W2sv = (float4*)W2s;
#pragma unroll
        for (int r = 0; r < SM_W2 / 4 / 256; r++)
            W2sv[tid + 256 * r] = W2v[tid + 256 * r];
    }
    for (int idx = tid; idx < TILE * H1; idx += 256) {
        const int r = idx >> 7;          // row in tile
        const int k = idx & (H1 - 1);    // feature
        As[k * (TILE + 1) + r] = g_A[(i0 + r) * H1 + k];
        Bs[k * (TILE + 1) + r] = g_B[(j0 + r) * H1 + k];
    }
    if (tid < H2) w3ds[tid] = W3[tid * 2 + 1] - W3[tid * 2 + 0];
    __syncthreads();

    // 2 pairs x 32 outputs: acc0 (j = 2*tjg), acc1 (j = 2*tjg+1)
    // acc*[m] holds outputs (32*oh + 2m, 32*oh + 2m + 1)
    unsigned long long acc0[16], acc1[16];
    {
        const unsigned long long* b2p = (const unsigned long long*)b2;
#pragma unroll
        for (int m = 0; m < 16; m++) {
            const unsigned long long bm = __ldg(&b2p[oh * 16 + m]);
            acc0[m] = bm;
            acc1[m] = bm;
        }
    }

    const float* w2base = W2s + oh * 32;   // this half's 32 columns

#pragma unroll 2
    for (int k = 0; k < H1; k++) {
        const float a  = As[k * (TILE + 1) + ti];
        const float b0 = Bs[k * (TILE + 1) + 2 * tjg];
        const float b1v = Bs[k * (TILE + 1) + 2 * tjg + 1];
        const float h0 = fmaxf(a + b0, 0.0f);
        const float h1 = fmaxf(a + b1v, 0.0f);
        unsigned long long hh0, hh1;
        asm("mov.b64 %0, {%1, %1};" : "=l"(hh0) : "f"(h0));
        asm("mov.b64 %0, {%1, %1};" : "=l"(hh1) : "f"(h1));
        const float* wrow = w2base + k * H2;
#pragma unroll
        for (int q = 0; q < 8; q++) {
            unsigned long long wlo, whi;
            // guaranteed single LDS.128 (broadcast: same address warp-wide)
            asm("ld.shared.v2.b64 {%0, %1}, [%2];"
                : "=l"(wlo), "=l"(whi)
                : "l"(__cvta_generic_to_shared(wrow + 4 * q)));
            asm("fma.rn.f32x2 %0, %1, %2, %0;" : "+l"(acc0[2*q  ]) : "l"(wlo), "l"(hh0));
            asm("fma.rn.f32x2 %0, %1, %2, %0;" : "+l"(acc0[2*q+1]) : "l"(whi), "l"(hh0));
            asm("fma.rn.f32x2 %0, %1, %2, %0;" : "+l"(acc1[2*q  ]) : "l"(wlo), "l"(hh1));
            asm("fma.rn.f32x2 %0, %1, %2, %0;" : "+l"(acc1[2*q+1]) : "l"(whi), "l"(hh1));
        }
    }

    // Partial epilogue: relu + dot with this half's w3 diff
    float p0 = 0.0f, p1 = 0.0f;
#pragma unroll
    for (int m = 0; m < 16; m++) {
        const float w3a = w3ds[oh * 32 + 2 * m];
        const float w3b = w3ds[oh * 32 + 2 * m + 1];
        float lo, hi;
        asm("mov.b64 {%0, %1}, %2;" : "=f"(lo), "=f"(hi) : "l"(acc0[m]));
        p0 = fmaf(fmaxf(lo, 0.0f), w3a, p0);
        p0 = fmaf(fmaxf(hi, 0.0f), w3b, p0);
        asm("mov.b64 {%0, %1}, %2;" : "=f"(lo), "=f"(hi) : "l"(acc1[m]));
        p1 = fmaf(fmaxf(lo, 0.0f), w3a, p1);
        p1 = fmaf(fmaxf(hi, 0.0f), w3b, p1);
    }
    part[oh * 256 + ti * 16 + 2 * tjg]     = p0;
    part[oh * 256 + ti * 16 + 2 * tjg + 1] = p1;
    __syncthreads();

    // Combine halves; threads of half 0 write 2 pairs each
    if (oh == 0) {
        const float base = __ldg(&b3[1]) - __ldg(&b3[0]);
        const int pi0 = ti * 16 + 2 * tjg;
        g_L[(i0 + ti) * n + (j0 + 2 * tjg)]     = base + part[pi0]     + part[256 + pi0];
        g_L[(i0 + ti) * n + (j0 + 2 * tjg + 1)] = base + part[pi0 + 1] + part[256 + pi0 + 1];
    }
}

// ---------------------------------------------------------------------------
// Kernel 3: out[i,j] = ( 0.5*(L[i,j]+L[j,i]) + g1 - g0 > 0 ) ? 1 : 0
// ---------------------------------------------------------------------------
__global__ void out_kernel(const float* __restrict__ u,
                           float* __restrict__ out,
                           int n)
{
    __shared__ float Lt[32][33];
    const int tx = threadIdx.x;         // 0..31
    const int ty = threadIdx.y;         // 0..7
    const int i0 = blockIdx.y * 32;
    const int j0 = blockIdx.x * 32;

#pragma unroll
    for (int r = 0; r < 4; r++) {
        const int jj = ty + 8 * r;
        Lt[jj][tx] = g_L[(j0 + jj) * n + (i0 + tx)];
    }
    __syncthreads();

#pragma unroll
    for (int r = 0; r < 4; r++) {
        const int ii = ty + 8 * r;
        const int i = i0 + ii;
        const int j = j0 + tx;
        const float lij = g_L[i * n + j];
        const float lji = Lt[tx][ii];
        const float lsym = 0.5f * (lij + lji);
        const float2 uv = ((const float2*)u)[i * n + j];
        const float g0 = -logf(-logf(uv.x + EPS_F) + EPS_F);
        const float g1 = -logf(-logf(uv.y + EPS_F) + EPS_F);
        out[i * n + j] = (lsym + g1 - g0 > 0.0f) ? 1.0f : 0.0f;
    }
}

// ---------------------------------------------------------------------------
extern "C" void kernel_launch(void* const* d_in, const int* in_sizes, int n_in,
                              void* d_out, int out_size)
{
    const float* X  = (const float*)d_in[0];
    const float* W1 = (const float*)d_in[1];
    const float* b1 = (const float*)d_in[2];
    const float* W2 = (const float*)d_in[3];
    const float* b2 = (const float*)d_in[4];
    const float* W3 = (const float*)d_in[5];
    const float* b3 = (const float*)d_in[6];
    const float* u  = (const float*)d_in[7];
    float* out = (float*)d_out;

    const int n = in_sizes[0] / D;   // 1024

    static bool attr_set = false;
    if (!attr_set) {
        cudaFuncSetAttribute(pair_kernel,
                             cudaFuncAttributeMaxDynamicSharedMemorySize,
                             SMEM_BYTES);
        attr_set = true;
    }

    ab_kernel<<<n, H1>>>(X, W1, b1, n);

    dim3 g2(n / TILE, n / TILE);
    pair_kernel<<<g2, 256, SMEM_BYTES>>>(W2, b2, W3, b3, n);

    dim3 b3d(32, 8);
    dim3 g3(n / 32, n / 32);
    out_kernel<<<g3, b3d>>>(u, out, n);
}

// round 5
// speedup vs baseline: 3.4134x; 2.3668x over previous
#include <cuda_runtime.h>
#include <cuda_bf16.h>
#include <cstdint>

#define D    64
#define H1   128
#define H2   64
#define NMAX 1024
#define EPS_F 1e-10f
#define THRESH 2e-3f
#define FIXCAP (1 << 20)

// Scratch (no allocations allowed)
__device__ float g_A[NMAX * H1];        // X @ W1[:D] + b1
__device__ float g_B[NMAX * H1];        // X @ W1[D:]
__device__ float g_L[NMAX * NMAX];      // logit diff per ordered pair
__device__ uint4 g_W2q[64 * 32];        // W2 bf16 splits packed as B-frag quads
__device__ unsigned int g_fixlist[FIXCAP];
__device__ int g_fixcnt;

// ---------------------------------------------------------------------------
// Kernel 1: A[i,k], B[i,k]. 8 rows per block to reuse W1 columns.
// ---------------------------------------------------------------------------
__global__ void ab_kernel(const float* __restrict__ X,
                          const float* __restrict__ W1,
                          const float* __restrict__ b1)
{
    __shared__ float xs[8][D];
    const int i0 = blockIdx.x * 8;
    const int k = threadIdx.x;           // 0..127

#pragma unroll
    for (int q = 0; q < 4; q++) {
        const int e = k + 128 * q;       // 0..511
        xs[e >> 6][e & 63] = X[(i0 + (e >> 6)) * D + (e & 63)];
    }
    __syncthreads();

    float a[8], b[8];
    const float bias = b1[k];
#pragma unroll
    for (int r = 0; r < 8; r++) { a[r] = bias; b[r] = 0.0f; }

#pragma unroll 4
    for (int d = 0; d < D; d++) {
        const float wA = W1[d * H1 + k];
        const float wB = W1[(D + d) * H1 + k];
#pragma unroll
        for (int r = 0; r < 8; r++) {
            a[r] = fmaf(xs[r][d], wA, a[r]);
            b[r] = fmaf(xs[r][d], wB, b[r]);
        }
    }
#pragma unroll
    for (int r = 0; r < 8; r++) {
        g_A[(i0 + r) * H1 + k] = a[r];
        g_B[(i0 + r) * H1 + k] = b[r];
    }
}

// ---------------------------------------------------------------------------
// Kernel 1b: split W2 into bf16 hi/mid, pack into B-fragment quads.
// quad[n][ks*4+t] = {b0hi, b0mid, b1hi, b1mid} where b0 covers k = 16ks+2t,+1
// and b1 covers k = 16ks+2t+8,+9 (each word = {lo: k even, hi: k odd}).
// Also resets the fixup counter.
// ---------------------------------------------------------------------------
__global__ void w2prep_kernel(const float* __restrict__ W2)
{
    const int idx = blockIdx.x * 256 + threadIdx.x;   // 0..4095
    if (idx == 0) g_fixcnt = 0;
    const int nn = idx >> 6;       // output col n (0..63)
    const int kk = idx & 63;       // k-pair index (0..63)
    const float w0 = W2[(2 * kk) * H2 + nn];
    const float w1 = W2[(2 * kk + 1) * H2 + nn];
    unsigned hiw, midw;
    asm("cvt.rn.satfinite.bf16x2.f32 %0, %1, %2;" : "=r"(hiw) : "f"(w1), "f"(w0));
    const float r0 = w0 - __uint_as_float(hiw << 16);
    const float r1 = w1 - __uint_as_float(hiw & 0xffff0000u);
    asm("cvt.rn.satfinite.bf16x2.f32 %0, %1, %2;" : "=r"(midw) : "f"(r1), "f"(r0));
    const int ks = kk >> 3;
    const int gg = kk & 7;
    const int t = gg & 3;
    const int half = gg >> 2;     // 0 -> b0 words, 1 -> b1 words
    ((uint2*)g_W2q)[(nn * 32 + ks * 4 + t) * 2 + half] = make_uint2(hiw, midw);
}

// ---------------------------------------------------------------------------
// Kernel 2: HMMA pair MLP. CTA = 256 thr (8 warps), tile = 16 i x 64 j
// (4 sub-tiles of 16x16 = 256 pairs). Warp w covers pairs with i = 2w,2w+1.
// 3 bf16 split products (hi*hi + hi*mid + mid*hi) -> fp32-accurate to ~1e-4.
// ---------------------------------------------------------------------------
#define SB_STRIDE 136                    // floats; (136*g+2t)%32 conflict-free
#define WQ_STRIDE 36                     // uint4;  (4g+t)%8 distinct per phase
#define SM_AS_OFF 0                      // 16*128 floats
#define SM_BS_OFF (16 * 128)             // 16*136 floats
#define SM_WQ_B   ((SM_BS_OFF + 16 * SB_STRIDE) * 4)   // byte offset, 16B-aligned
#define SM_B2_B   (SM_WQ_B + 64 * WQ_STRIDE * 16)
#define SM_W3_B   (SM_B2_B + 256)
#define SMEM_BYTES (SM_W3_B + 256)

__device__ __forceinline__ void mma_bf16(float* c, const unsigned* a,
                                         unsigned b0, unsigned b1)
{
    asm("mma.sync.aligned.m16n8k16.row.col.f32.bf16.bf16.f32 "
        "{%0,%1,%2,%3}, {%4,%5,%6,%7}, {%8,%9}, {%0,%1,%2,%3};"
        : "+f"(c[0]), "+f"(c[1]), "+f"(c[2]), "+f"(c[3])
        : "r"(a[0]), "r"(a[1]), "r"(a[2]), "r"(a[3]), "r"(b0), "r"(b1));
}

__device__ __forceinline__ void hsplit(float2 a, float2 b,
                                       unsigned& hi, unsigned& mid)
{
    const float h0 = fmaxf(a.x + b.x, 0.0f);
    const float h1 = fmaxf(a.y + b.y, 0.0f);
    asm("cvt.rn.satfinite.bf16x2.f32 %0, %1, %2;" : "=r"(hi) : "f"(h1), "f"(h0));
    const float r0 = h0 - __uint_as_float(hi << 16);
    const float r1 = h1 - __uint_as_float(hi & 0xffff0000u);
    asm("cvt.rn.satfinite.bf16x2.f32 %0, %1, %2;" : "=r"(mid) : "f"(r1), "f"(r0));
}

__global__ __launch_bounds__(256)
void pair_mma_kernel(const float* __restrict__ b2,
                     const float* __restrict__ W3,
                     const float* __restrict__ b3,
                     int n)
{
    extern __shared__ unsigned char smraw[];
    float* As  = (float*)smraw;                     // [16][128]
    float* Bs  = (float*)smraw + SM_BS_OFF;         // [16][136]
    uint4* W2q = (uint4*)(smraw + SM_WQ_B);         // [64][36]
    float* b2s = (float*)(smraw + SM_B2_B);         // [64]
    float* w3s = (float*)(smraw + SM_W3_B);         // [64]

    const int tid = threadIdx.x;
    const int w = tid >> 5;
    const int l = tid & 31;
    const int g = l >> 2;          // groupID 0..7
    const int t = l & 3;

    const int i0 = blockIdx.y * 16;

    // ---- stage As (16x128 fp32) and W2 quads (64x32 uint4), b2/w3 ----
    {
        const float4* srcA = (const float4*)g_A;
#pragma unroll
        for (int q = 0; q < 2; q++) {
            const int e = tid + q * 256;         // 0..511 float4s
            const int r = e >> 5, c4 = e & 31;
            *(float4*)&As[r * 128 + c4 * 4] = srcA[(i0 + r) * 32 + c4];
        }
#pragma unroll
        for (int q = 0; q < 8; q++) {
            const int e = tid + q * 256;         // 0..2047
            const int nn = e >> 5, c = e & 31;
            W2q[nn * WQ_STRIDE + c] = g_W2q[nn * 32 + c];
        }
        if (tid < 64) {
            b2s[tid] = b2[tid];
            w3s[tid] = W3[tid * 2 + 1] - W3[tid * 2];
        }
    }
    const float b3d = __ldg(&b3[1]) - __ldg(&b3[0]);

    for (int tt = 0; tt < 4; tt++) {
        const int j0 = (blockIdx.x * 4 + tt) * 16;
        __syncthreads();   // protect Bs (and cover prologue on tt=0)
        {
            const float2* srcB = (const float2*)g_B;
#pragma unroll
            for (int q = 0; q < 4; q++) {
                const int e = tid + q * 256;     // 0..1023 float2s
                const int r = e >> 6, c2 = e & 63;
                *(float2*)&Bs[r * SB_STRIDE + c2 * 2] = srcB[(j0 + r) * 64 + c2];
            }
        }
        __syncthreads();

        float acc[2][8][4];
#pragma unroll
        for (int f = 0; f < 2; f++)
#pragma unroll
            for (int nb = 0; nb < 8; nb++)
#pragma unroll
                for (int c = 0; c < 4; c++) acc[f][nb][c] = 0.0f;

#pragma unroll
        for (int ks = 0; ks < 8; ks++) {
            const int k0 = ks * 16;
            const float2 blo_g  = *(const float2*)&Bs[g * SB_STRIDE + k0 + 2 * t];
            const float2 bhi_g  = *(const float2*)&Bs[g * SB_STRIDE + k0 + 2 * t + 8];
            const float2 blo_g8 = *(const float2*)&Bs[(g + 8) * SB_STRIDE + k0 + 2 * t];
            const float2 bhi_g8 = *(const float2*)&Bs[(g + 8) * SB_STRIDE + k0 + 2 * t + 8];

            unsigned ahi[2][4], amid[2][4];
#pragma unroll
            for (int f = 0; f < 2; f++) {
                const float2 alo = *(const float2*)&As[(2 * w + f) * 128 + k0 + 2 * t];
                const float2 ah2 = *(const float2*)&As[(2 * w + f) * 128 + k0 + 2 * t + 8];
                hsplit(alo, blo_g,  ahi[f][0], amid[f][0]);  // row g
                hsplit(alo, blo_g8, ahi[f][1], amid[f][1]);  // row g+8
                hsplit(ah2, bhi_g,  ahi[f][2], amid[f][2]);  // row g,  k+8
                hsplit(ah2, bhi_g8, ahi[f][3], amid[f][3]);  // row g+8,k+8
            }
#pragma unroll
            for (int nb = 0; nb < 8; nb++) {
                const uint4 q = W2q[(nb * 8 + g) * WQ_STRIDE + ks * 4 + t];
#pragma unroll
                for (int f = 0; f < 2; f++) {
                    mma_bf16(acc[f][nb], ahi[f],  q.x, q.z);   // hi*hi
                    mma_bf16(acc[f][nb], ahi[f],  q.y, q.w);   // hi*mid
                    mma_bf16(acc[f][nb], amid[f], q.x, q.z);   // mid*hi
                }
            }
        }

        // ---- epilogue: +b2, relu, dot w3diff, reduce over 4 lanes ----
        float s[2][2] = {{0.f, 0.f}, {0.f, 0.f}};
#pragma unroll
        for (int nb = 0; nb < 8; nb++) {
            const float2 bb = *(const float2*)&b2s[nb * 8 + 2 * t];
            const float2 ww = *(const float2*)&w3s[nb * 8 + 2 * t];
#pragma unroll
            for (int f = 0; f < 2; f++) {
                s[f][0] += fmaxf(acc[f][nb][0] + bb.x, 0.f) * ww.x
                         + fmaxf(acc[f][nb][1] + bb.y, 0.f) * ww.y;
                s[f][1] += fmaxf(acc[f][nb][2] + bb.x, 0.f) * ww.x
                         + fmaxf(acc[f][nb][3] + bb.y, 0.f) * ww.y;
            }
        }
#pragma unroll
        for (int f = 0; f < 2; f++)
#pragma unroll
            for (int r = 0; r < 2; r++) {
                float v = s[f][r];
                v += __shfl_xor_sync(0xffffffffu, v, 1);
                v += __shfl_xor_sync(0xffffffffu, v, 2);
                if (t == 0)
                    g_L[(i0 + 2 * w + f) * n + (j0 + g + 8 * r)] = v + b3d;
            }
    }
}

// ---------------------------------------------------------------------------
// Kernel 3: out[i,j] = (0.5*(L[i,j]+L[j,i]) + g1 - g0 > 0); flag near-margin.
// ---------------------------------------------------------------------------
__global__ void out_kernel(const float* __restrict__ u,
                           float* __restrict__ out,
                           int n)
{
    __shared__ float Lt[32][33];
    const int tx = threadIdx.x;
    const int ty = threadIdx.y;
    const int i0 = blockIdx.y * 32;
    const int j0 = blockIdx.x * 32;

#pragma unroll
    for (int r = 0; r < 4; r++) {
        const int jj = ty + 8 * r;
        Lt[jj][tx] = g_L[(j0 + jj) * n + (i0 + tx)];
    }
    __syncthreads();

#pragma unroll
    for (int r = 0; r < 4; r++) {
        const int ii = ty + 8 * r;
        const int i = i0 + ii;
        const int j = j0 + tx;
        const float lij = g_L[i * n + j];
        const float lji = Lt[tx][ii];
        const float lsym = 0.5f * (lij + lji);
        const float2 uv = ((const float2*)u)[i * n + j];
        const float g0 = -__logf(-__logf(uv.x + EPS_F) + EPS_F);
        const float g1 = -__logf(-__logf(uv.y + EPS_F) + EPS_F);
        const float z = lsym + g1 - g0;
        out[i * n + j] = (z > 0.0f) ? 1.0f : 0.0f;
        if (fabsf(z) < THRESH) {
            const int slot = atomicAdd(&g_fixcnt, 1);
            if (slot < FIXCAP) g_fixlist[slot] = (unsigned)(i << 10 | j);
        }
    }
}

// ---------------------------------------------------------------------------
// Kernel 4: exact fp32 recompute for flagged near-margin pairs.
// ---------------------------------------------------------------------------
__global__ void fixup_kernel(const float* __restrict__ W2,
                             const float* __restrict__ b2,
                             const float* __restrict__ W3,
                             const float* __restrict__ b3,
                             const float* __restrict__ u,
                             float* __restrict__ out,
                             int n)
{
    __shared__ float h1a[H1], h1b[H1], reda[H2], redb[H2];
    const int cnt = min(g_fixcnt, FIXCAP);
    const int c = threadIdx.x;   // 0..63

    for (int idx = blockIdx.x; idx < cnt; idx += gridDim.x) {
        const unsigned pk = g_fixlist[idx];
        const int i = pk >> 10, j = pk & 1023;

        for (int k = c; k < H1; k += 64) {
            h1a[k] = fmaxf(g_A[i * H1 + k] + g_B[j * H1 + k], 0.f);
            h1b[k] = fmaxf(g_A[j * H1 + k] + g_B[i * H1 + k], 0.f);
        }
        __syncthreads();

        float aa = b2[c], ab = b2[c];
        for (int k = 0; k < H1; k++) {
            const float wv = W2[k * H2 + c];
            aa = fmaf(h1a[k], wv, aa);
            ab = fmaf(h1b[k], wv, ab);
        }
        const float w3d = W3[c * 2 + 1] - W3[c * 2];
        reda[c] = fmaxf(aa, 0.f) * w3d;
        redb[c] = fmaxf(ab, 0.f) * w3d;
        __syncthreads();

        if (c == 0) {
            float La = 0.f, Lb = 0.f;
            for (int q = 0; q < H2; q++) { La += reda[q]; Lb += redb[q]; }
            const float b3d = b3[1] - b3[0];
            const float lsym = 0.5f * (La + Lb) + b3d;
            const float2 uv = ((const float2*)u)[i * n + j];
            const float g0 = -logf(-logf(uv.x + EPS_F) + EPS_F);
            const float g1 = -logf(-logf(uv.y + EPS_F) + EPS_F);
            out[i * n + j] = (lsym + g1 - g0 > 0.f) ? 1.0f : 0.0f;
        }
        __syncthreads();
    }
}

// ---------------------------------------------------------------------------
extern "C" void kernel_launch(void* const* d_in, const int* in_sizes, int n_in,
                              void* d_out, int out_size)
{
    const float* X  = (const float*)d_in[0];
    const float* W1 = (const float*)d_in[1];
    const float* b1 = (const float*)d_in[2];
    const float* W2 = (const float*)d_in[3];
    const float* b2 = (const float*)d_in[4];
    const float* W3 = (const float*)d_in[5];
    const float* b3 = (const float*)d_in[6];
    const float* u  = (const float*)d_in[7];
    float* out = (float*)d_out;

    const int n = in_sizes[0] / D;   // 1024

    static bool attr_set = false;
    if (!attr_set) {
        cudaFuncSetAttribute(pair_mma_kernel,
                             cudaFuncAttributeMaxDynamicSharedMemorySize,
                             SMEM_BYTES);
        attr_set = true;
    }

    ab_kernel<<<n / 8, 128>>>(X, W1, b1);
    w2prep_kernel<<<16, 256>>>(W2);

    dim3 g2(n / 64, n / 16);         // x: j-groups (4 tiles each), y: i-blocks
    pair_mma_kernel<<<g2, 256, SMEM_BYTES>>>(b2, W3, b3, n);

    dim3 b3d_(32, 8);
    dim3 g3(n / 32, n / 32);
    out_kernel<<<g3, b3d_>>>(u, out, n);

    fixup_kernel<<<256, 64>>>(W2, b2, W3, b3, u, out, n);
}

// round 8
// speedup vs baseline: 3.5401x; 1.0371x over previous
#include <cuda_runtime.h>
#include <cuda_bf16.h>
#include <cstdint>

#define D    64
#define H1   128
#define H2   64
#define NMAX 1024
#define EPS_F 1e-10f
#define THRESH 2e-3f
#define FIXCAP (1 << 20)

// Scratch (no allocations allowed)
__device__ float g_A[NMAX * H1];        // X @ W1[:D] + b1
__device__ float g_B[NMAX * H1];        // X @ W1[D:]
__device__ float g_L[NMAX * NMAX];      // logit diff per ordered pair
__device__ uint4 g_W2q[64 * 32];        // W2 bf16 splits packed as B-frag quads
__device__ unsigned int g_fixlist[FIXCAP];
__device__ int g_fixcnt;

// ---------------------------------------------------------------------------
// Kernel 1: A[i,k], B[i,k]. 2 rows per block, 256 threads (grid 512).
// ---------------------------------------------------------------------------
__global__ void ab_kernel(const float* __restrict__ X,
                          const float* __restrict__ W1,
                          const float* __restrict__ b1)
{
    __shared__ float xs[2][D];
    const int i0 = blockIdx.x * 2;
    const int tid = threadIdx.x;
    const int r = tid >> 7;              // row 0/1
    const int k = tid & 127;

    if (tid < 128) xs[tid >> 6][tid & 63] = X[i0 * D + tid];
    __syncthreads();

    float a = b1[k];
    float b = 0.0f;
#pragma unroll
    for (int d = 0; d < D; d++) {
        const float x = xs[r][d];
        a = fmaf(x, W1[d * H1 + k], a);
        b = fmaf(x, W1[(D + d) * H1 + k], b);
    }
    g_A[(i0 + r) * H1 + k] = a;
    g_B[(i0 + r) * H1 + k] = b;
}

// ---------------------------------------------------------------------------
// Kernel 1b: split W2 into bf16 hi/mid, pack into B-fragment quads.
// quad[n][ks*4+t] = {b0hi, b0mid, b1hi, b1mid} where b0 covers k = 16ks+2t,+1
// and b1 covers k = 16ks+2t+8,+9 (each word = {lo: k even, hi: k odd}).
// Also resets the fixup counter.
// ---------------------------------------------------------------------------
__global__ void w2prep_kernel(const float* __restrict__ W2)
{
    const int idx = blockIdx.x * 256 + threadIdx.x;   // 0..4095
    if (idx == 0) g_fixcnt = 0;
    const int nn = idx >> 6;       // output col n (0..63)
    const int kk = idx & 63;       // k-pair index (0..63)
    const float w0 = W2[(2 * kk) * H2 + nn];
    const float w1 = W2[(2 * kk + 1) * H2 + nn];
    unsigned hiw, midw;
    asm("cvt.rn.satfinite.bf16x2.f32 %0, %1, %2;" : "=r"(hiw) : "f"(w1), "f"(w0));
    const float r0 = w0 - __uint_as_float(hiw << 16);
    const float r1 = w1 - __uint_as_float(hiw & 0xffff0000u);
    asm("cvt.rn.satfinite.bf16x2.f32 %0, %1, %2;" : "=r"(midw) : "f"(r1), "f"(r0));
    const int ks = kk >> 3;
    const int gg = kk & 7;
    const int t = gg & 3;
    const int half = gg >> 2;     // 0 -> b0 words, 1 -> b1 words
    ((uint2*)g_W2q)[(nn * 32 + ks * 4 + t) * 2 + half] = make_uint2(hiw, midw);
}

// ---------------------------------------------------------------------------
// Kernel 2: HMMA pair MLP. CTA = 256 thr (8 warps), tile = 16 i x 64 j
// (4 sub-tiles of 16x16). Warp w covers pairs with i = 2w,2w+1.
// 3 bf16 split products (hi*hi + hi*mid + mid*hi) -> fp32-accurate to ~1e-4.
// MMA issue is product-major over 4-nb blocks: 8 independent MMAs between
// accumulator reuses (breaks the HMMA RAW chains of the previous version).
// ---------------------------------------------------------------------------
#define SB_STRIDE 136                    // floats; (136*g+2t)%32 conflict-free
#define WQ_STRIDE 36                     // uint4;  (4g+t)%8 distinct per phase
#define SM_AS_OFF 0                      // 16*128 floats
#define SM_BS_OFF (16 * 128)             // 16*136 floats
#define SM_WQ_B   ((SM_BS_OFF + 16 * SB_STRIDE) * 4)   // byte offset, 16B-aligned
#define SM_B2_B   (SM_WQ_B + 64 * WQ_STRIDE * 16)
#define SM_W3_B   (SM_B2_B + 256)
#define SMEM_BYTES (SM_W3_B + 256)

__device__ __forceinline__ void mma_bf16(float* c, const unsigned* a,
                                         unsigned b0, unsigned b1)
{
    asm("mma.sync.aligned.m16n8k16.row.col.f32.bf16.bf16.f32 "
        "{%0,%1,%2,%3}, {%4,%5,%6,%7}, {%8,%9}, {%0,%1,%2,%3};"
        : "+f"(c[0]), "+f"(c[1]), "+f"(c[2]), "+f"(c[3])
        : "r"(a[0]), "r"(a[1]), "r"(a[2]), "r"(a[3]), "r"(b0), "r"(b1));
}

__device__ __forceinline__ void hsplit(float2 a, float2 b,
                                       unsigned& hi, unsigned& mid)
{
    const float h0 = fmaxf(a.x + b.x, 0.0f);
    const float h1 = fmaxf(a.y + b.y, 0.0f);
    asm("cvt.rn.satfinite.bf16x2.f32 %0, %1, %2;" : "=r"(hi) : "f"(h1), "f"(h0));
    const float r0 = h0 - __uint_as_float(hi << 16);
    const float r1 = h1 - __uint_as_float(hi & 0xffff0000u);
    asm("cvt.rn.satfinite.bf16x2.f32 %0, %1, %2;" : "=r"(mid) : "f"(r1), "f"(r0));
}

__global__ __launch_bounds__(256)
void pair_mma_kernel(const float* __restrict__ b2,
                     const float* __restrict__ W3,
                     const float* __restrict__ b3,
                     int n)
{
    extern __shared__ unsigned char smraw[];
    float* As  = (float*)smraw;                     // [16][128]
    float* Bs  = (float*)smraw + SM_BS_OFF;         // [16][136]
    uint4* W2q = (uint4*)(smraw + SM_WQ_B);         // [64][36]
    float* b2s = (float*)(smraw + SM_B2_B);         // [64]
    float* w3s = (float*)(smraw + SM_W3_B);         // [64]

    const int tid = threadIdx.x;
    const int w = tid >> 5;
    const int l = tid & 31;
    const int g = l >> 2;          // groupID 0..7
    const int t = l & 3;

    const int i0 = blockIdx.y * 16;

    // ---- stage As (16x128 fp32) and W2 quads (64x32 uint4), b2/w3 ----
    {
        const float4* srcA = (const float4*)g_A;
#pragma unroll
        for (int q = 0; q < 2; q++) {
            const int e = tid + q * 256;         // 0..511 float4s
            const int r = e >> 5, c4 = e & 31;
            *(float4*)&As[r * 128 + c4 * 4] = srcA[(i0 + r) * 32 + c4];
        }
#pragma unroll
        for (int q = 0; q < 8; q++) {
            const int e = tid + q * 256;         // 0..2047
            const int nn = e >> 5, c = e & 31;
            W2q[nn * WQ_STRIDE + c] = g_W2q[nn * 32 + c];
        }
        if (tid < 64) {
            b2s[tid] = b2[tid];
            w3s[tid] = W3[tid * 2 + 1] - W3[tid * 2];
        }
    }
    const float b3d = __ldg(&b3[1]) - __ldg(&b3[0]);

    for (int tt = 0; tt < 4; tt++) {
        const int j0 = (blockIdx.x * 4 + tt) * 16;
        __syncthreads();   // protect Bs (and cover prologue on tt=0)
        {
            const float2* srcB = (const float2*)g_B;
#pragma unroll
            for (int q = 0; q < 4; q++) {
                const int e = tid + q * 256;     // 0..1023 float2s
                const int r = e >> 6, c2 = e & 63;
                *(float2*)&Bs[r * SB_STRIDE + c2 * 2] = srcB[(j0 + r) * 64 + c2];
            }
        }
        __syncthreads();

        float acc[2][8][4];
#pragma unroll
        for (int f = 0; f < 2; f++)
#pragma unroll
            for (int nb = 0; nb < 8; nb++)
#pragma unroll
                for (int c = 0; c < 4; c++) acc[f][nb][c] = 0.0f;

#pragma unroll
        for (int ks = 0; ks < 8; ks++) {
            const int k0 = ks * 16;
            const float2 blo_g  = *(const float2*)&Bs[g * SB_STRIDE + k0 + 2 * t];
            const float2 bhi_g  = *(const float2*)&Bs[g * SB_STRIDE + k0 + 2 * t + 8];
            const float2 blo_g8 = *(const float2*)&Bs[(g + 8) * SB_STRIDE + k0 + 2 * t];
            const float2 bhi_g8 = *(const float2*)&Bs[(g + 8) * SB_STRIDE + k0 + 2 * t + 8];

            unsigned ahi[2][4], amid[2][4];
#pragma unroll
            for (int f = 0; f < 2; f++) {
                const float2 alo = *(const float2*)&As[(2 * w + f) * 128 + k0 + 2 * t];
                const float2 ah2 = *(const float2*)&As[(2 * w + f) * 128 + k0 + 2 * t + 8];
                hsplit(alo, blo_g,  ahi[f][0], amid[f][0]);  // row g
                hsplit(alo, blo_g8, ahi[f][1], amid[f][1]);  // row g+8
                hsplit(ah2, bhi_g,  ahi[f][2], amid[f][2]);  // row g,  k+8
                hsplit(ah2, bhi_g8, ahi[f][3], amid[f][3]);  // row g+8,k+8
            }

            // Two 4-nb blocks; within each: batched quad loads, then
            // product-major MMA issue (8 independent MMAs between reuses).
#pragma unroll
            for (int hb = 0; hb < 2; hb++) {
                uint4 q[4];
#pragma unroll
                for (int nq = 0; nq < 4; nq++)
                    q[nq] = W2q[((hb * 4 + nq) * 8 + g) * WQ_STRIDE + ks * 4 + t];
#pragma unroll
                for (int nq = 0; nq < 4; nq++) {           // hi*hi
#pragma unroll
                    for (int f = 0; f < 2; f++)
                        mma_bf16(acc[f][hb * 4 + nq], ahi[f],  q[nq].x, q[nq].z);
                }
#pragma unroll
                for (int nq = 0; nq < 4; nq++) {           // hi*mid
#pragma unroll
                    for (int f = 0; f < 2; f++)
                        mma_bf16(acc[f][hb * 4 + nq], ahi[f],  q[nq].y, q[nq].w);
                }
#pragma unroll
                for (int nq = 0; nq < 4; nq++) {           // mid*hi
#pragma unroll
                    for (int f = 0; f < 2; f++)
                        mma_bf16(acc[f][hb * 4 + nq], amid[f], q[nq].x, q[nq].z);
                }
            }
        }

        // ---- epilogue: +b2, relu, dot w3diff, reduce over 4 lanes ----
        float s[2][2] = {{0.f, 0.f}, {0.f, 0.f}};
#pragma unroll
        for (int nb = 0; nb < 8; nb++) {
            const float2 bb = *(const float2*)&b2s[nb * 8 + 2 * t];
            const float2 ww = *(const float2*)&w3s[nb * 8 + 2 * t];
#pragma unroll
            for (int f = 0; f < 2; f++) {
                s[f][0] += fmaxf(acc[f][nb][0] + bb.x, 0.f) * ww.x
                         + fmaxf(acc[f][nb][1] + bb.y, 0.f) * ww.y;
                s[f][1] += fmaxf(acc[f][nb][2] + bb.x, 0.f) * ww.x
                         + fmaxf(acc[f][nb][3] + bb.y, 0.f) * ww.y;
            }
        }
#pragma unroll
        for (int f = 0; f < 2; f++)
#pragma unroll
            for (int r = 0; r < 2; r++) {
                float v = s[f][r];
                v += __shfl_xor_sync(0xffffffffu, v, 1);
                v += __shfl_xor_sync(0xffffffffu, v, 2);
                if (t == 0)
                    g_L[(i0 + 2 * w + f) * n + (j0 + g + 8 * r)] = v + b3d;
            }
    }
}

// ---------------------------------------------------------------------------
// Kernel 3: out[i,j] = (0.5*(L[i,j]+L[j,i]) + g1 - g0 > 0); flag near-margin.
// ---------------------------------------------------------------------------
__global__ void out_kernel(const float* __restrict__ u,
                           float* __restrict__ out,
                           int n)
{
    __shared__ float Lt[32][33];
    const int tx = threadIdx.x;
    const int ty = threadIdx.y;
    const int i0 = blockIdx.y * 32;
    const int j0 = blockIdx.x * 32;

#pragma unroll
    for (int r = 0; r < 4; r++) {
        const int jj = ty + 8 * r;
        Lt[jj][tx] = g_L[(j0 + jj) * n + (i0 + tx)];
    }
    __syncthreads();

#pragma unroll
    for (int r = 0; r < 4; r++) {
        const int ii = ty + 8 * r;
        const int i = i0 + ii;
        const int j = j0 + tx;
        const float lij = g_L[i * n + j];
        const float lji = Lt[tx][ii];
        const float lsym = 0.5f * (lij + lji);
        const float2 uv = ((const float2*)u)[i * n + j];
        const float g0 = -__logf(-__logf(uv.x + EPS_F) + EPS_F);
        const float g1 = -__logf(-__logf(uv.y + EPS_F) + EPS_F);
        const float z = lsym + g1 - g0;
        out[i * n + j] = (z > 0.0f) ? 1.0f : 0.0f;
        if (fabsf(z) < THRESH) {
            const int slot = atomicAdd(&g_fixcnt, 1);
            if (slot < FIXCAP) g_fixlist[slot] = (unsigned)(i << 10 | j);
        }
    }
}

// ---------------------------------------------------------------------------
// Kernel 4: exact fp32 recompute for flagged near-margin pairs.
// ---------------------------------------------------------------------------
__global__ void fixup_kernel(const float* __restrict__ W2,
                             const float* __restrict__ b2,
                             const float* __restrict__ W3,
                             const float* __restrict__ b3,
                             const float* __restrict__ u,
                             float* __restrict__ out,
                             int n)
{
    __shared__ float h1a[H1], h1b[H1], reda[H2], redb[H2];
    const int cnt = min(g_fixcnt, FIXCAP);
    const int c = threadIdx.x;   // 0..63

    for (int idx = blockIdx.x; idx < cnt; idx += gridDim.x) {
        const unsigned pk = g_fixlist[idx];
        const int i = pk >> 10, j = pk & 1023;

        for (int k = c; k < H1; k += 64) {
            h1a[k] = fmaxf(g_A[i * H1 + k] + g_B[j * H1 + k], 0.f);
            h1b[k] = fmaxf(g_A[j * H1 + k] + g_B[i * H1 + k], 0.f);
        }
        __syncthreads();

        float aa = b2[c], ab = b2[c];
        for (int k = 0; k < H1; k++) {
            const float wv = W2[k * H2 + c];
            aa = fmaf(h1a[k], wv, aa);
            ab = fmaf(h1b[k], wv, ab);
        }
        const float w3d = W3[c * 2 + 1] - W3[c * 2];
        reda[c] = fmaxf(aa, 0.f) * w3d;
        redb[c] = fmaxf(ab, 0.f) * w3d;
        __syncthreads();

        if (c == 0) {
            float La = 0.f, Lb = 0.f;
            for (int q = 0; q < H2; q++) { La += reda[q]; Lb += redb[q]; }
            const float b3d = b3[1] - b3[0];
            const float lsym = 0.5f * (La + Lb) + b3d;
            const float2 uv = ((const float2*)u)[i * n + j];
            const float g0 = -logf(-logf(uv.x + EPS_F) + EPS_F);
            const float g1 = -logf(-logf(uv.y + EPS_F) + EPS_F);
            out[i * n + j] = (lsym + g1 - g0 > 0.f) ? 1.0f : 0.0f;
        }
        __syncthreads();
    }
}

// ---------------------------------------------------------------------------
extern "C" void kernel_launch(void* const* d_in, const int* in_sizes, int n_in,
                              void* d_out, int out_size)
{
    const float* X  = (const float*)d_in[0];
    const float* W1 = (const float*)d_in[1];
    const float* b1 = (const float*)d_in[2];
    const float* W2 = (const float*)d_in[3];
    const float* b2 = (const float*)d_in[4];
    const float* W3 = (const float*)d_in[5];
    const float* b3 = (const float*)d_in[6];
    const float* u  = (const float*)d_in[7];
    float* out = (float*)d_out;

    const int n = in_sizes[0] / D;   // 1024

    static bool attr_set = false;
    if (!attr_set) {
        cudaFuncSetAttribute(pair_mma_kernel,
                             cudaFuncAttributeMaxDynamicSharedMemorySize,
                             SMEM_BYTES);
        attr_set = true;
    }

    ab_kernel<<<n / 2, 256>>>(X, W1, b1);
    w2prep_kernel<<<16, 256>>>(W2);

    dim3 g2(n / 64, n / 16);         // x: j-groups (4 tiles each), y: i-blocks
    pair_mma_kernel<<<g2, 256, SMEM_BYTES>>>(b2, W3, b3, n);

    dim3 b3d_(32, 8);
    dim3 g3(n / 32, n / 32);
    out_kernel<<<g3, b3d_>>>(u, out, n);

    fixup_kernel<<<256, 64>>>(W2, b2, W3, b3, u, out, n);
}